// round 3
// baseline (speedup 1.0000x reference)
#include <cuda_runtime.h>
#include <math.h>

#define HD   100
#define OBS  114
#define RPB  8          // rows (warps) per block

// per-warp smem layout (float offsets)
#define S_RAW 0         // 116 (114 used)
#define S_SE  116       // 100
#define S_ENC 216       // 47*100 = 4700  (oth:0..14, lm:15..30, gl:31..46)
#define S_X   4916      // 400 (gi|va|vl|vg)
#define S_H   5316      // 100
#define S_ATT 5416      // 32
#define SWARP 5448      // floats per warp region (16B-aligned: %4==0)
#define SMEM_BYTES (RPB * SWARP * 4)

__device__ __forceinline__ float4 ld4(const float* p) { return *reinterpret_cast<const float4*>(p); }
__device__ __forceinline__ void   st4(float* p, float4 v) { *reinterpret_cast<float4*>(p) = v; }
__device__ __forceinline__ float4 f4z() { return make_float4(0.f, 0.f, 0.f, 0.f); }
__device__ __forceinline__ float4 fma4(float s, float4 w, float4 a) {
    a.x = fmaf(s, w.x, a.x); a.y = fmaf(s, w.y, a.y);
    a.z = fmaf(s, w.z, a.z); a.w = fmaf(s, w.w, a.w);
    return a;
}
__device__ __forceinline__ float wsum(float v) {
#pragma unroll
    for (int o = 16; o; o >>= 1) v += __shfl_xor_sync(0xffffffffu, v, o);
    return v;
}
__device__ __forceinline__ float wmax(float v) {
#pragma unroll
    for (int o = 16; o; o >>= 1) v = fmaxf(v, __shfl_xor_sync(0xffffffffu, v, o));
    return v;
}
__device__ __forceinline__ float4 tanh4(float4 v) {
    v.x = tanhf(v.x); v.y = tanhf(v.y); v.z = tanhf(v.z); v.w = tanhf(v.w);
    return v;
}
// LayerNorm over 100 features spread across lanes 0..24 (4 each)
__device__ __forceinline__ float4 ln4(float4 pre, float4 g, float4 b, bool act) {
    float s  = act ? (pre.x + pre.y + pre.z + pre.w) : 0.f;
    float sq = act ? (pre.x * pre.x + pre.y * pre.y + pre.z * pre.z + pre.w * pre.w) : 0.f;
    s = wsum(s); sq = wsum(sq);
    float m   = s * 0.01f;
    float var = sq * 0.01f - m * m;
    float r   = rsqrtf(var + 1e-5f);
    float4 o;
    o.x = (pre.x - m) * r * g.x + b.x;
    o.y = (pre.y - m) * r * g.y + b.y;
    o.z = (pre.z - m) * r * g.z + b.z;
    o.w = (pre.w - m) * r * g.w + b.w;
    return o;
}

// one attention head: logits over nn encoder rows, softmax, weighted sum -> x segment
__device__ __forceinline__ void attn_head(float* sw, int encBase, int nn, float4 q,
                                          float* xout, bool act, int lane, int j0) {
    float mylog = 0.f;
    for (int n = 0; n < nn; n++) {
        float p = 0.f;
        if (act) {
            float4 e = ld4(sw + encBase + n * HD + j0);
            p = q.x * e.x + q.y * e.y + q.z * e.z + q.w * e.w;
        }
        p = wsum(p);
        if (lane == n) mylog = p;
    }
    float mx  = wmax(lane < nn ? mylog : -1e30f);
    float ex  = lane < nn ? expf(mylog - mx) : 0.f;
    float den = wsum(ex);
    if (lane < nn) sw[S_ATT + lane] = ex / den;
    __syncwarp();
    if (act) {
        float4 v = f4z();
        for (int n = 0; n < nn; n++) {
            float a  = sw[S_ATT + n];
            float4 e = ld4(sw + encBase + n * HD + j0);
            v = fma4(a, e, v);
        }
        st4(xout + j0, v);
    }
    __syncwarp();
}

extern __shared__ float smem[];

__global__ void __launch_bounds__(RPB * 32, 1) obsenc_kernel(
    const float* __restrict__ inp, int B,
    const float* __restrict__ sW,  const float* __restrict__ sb,  const float* __restrict__ sg,  const float* __restrict__ sbe,
    const float* __restrict__ oW,  const float* __restrict__ ob,  const float* __restrict__ og,  const float* __restrict__ obe,
    const float* __restrict__ lW,  const float* __restrict__ lb,  const float* __restrict__ lg,  const float* __restrict__ lbe,
    const float* __restrict__ gW,  const float* __restrict__ gb,  const float* __restrict__ gg,  const float* __restrict__ gbe,
    const float* __restrict__ Ac,  const float* __restrict__ Lc,
    const float* __restrict__ fcW, const float* __restrict__ fcb, const float* __restrict__ fcg, const float* __restrict__ fcbe,
    const float* __restrict__ f1W, const float* __restrict__ f1b, const float* __restrict__ f1g, const float* __restrict__ f1be,
    const float* __restrict__ f2W, const float* __restrict__ f2b, const float* __restrict__ f2g, const float* __restrict__ f2be,
    float* __restrict__ out)
{
    const int warp = threadIdx.x >> 5;
    const int lane = threadIdx.x & 31;
    const int row  = blockIdx.x * RPB + warp;
    if (row >= B) return;                   // whole-warp exit; no block syncs used

    float* sw_ = smem + warp * SWARP;
    const bool act = lane < 25;
    const int  j0  = lane * 4;              // features j0..j0+3 (valid when act)

    // ---- load raw row into smem ----
    const float* rp = inp + (long)row * OBS;
    for (int i = lane; i < OBS; i += 32) sw_[S_RAW + i] = rp[i];
    __syncwarp();

    // ---- self encoder: 4 -> 100, tanh, LN ----
    {
        float4 acc = f4z(), g4 = f4z(), b4 = f4z();
        if (act) {
            acc = ld4(sb + j0);
#pragma unroll
            for (int k = 0; k < 4; k++) {
                float xv = sw_[S_RAW + k];
                acc = fma4(xv, ld4(sW + k * HD + j0), acc);
            }
            acc = tanh4(acc);
            g4 = ld4(sg + j0); b4 = ld4(sbe + j0);
        }
        float4 se = ln4(acc, g4, b4, act);
        if (act) st4(sw_ + S_SE + j0, se);
    }
    __syncwarp();

    // ---- small encoders: oth (15), lm (16), gl (16) -> enc smem ----
    {
        float4 w0 = f4z(), w1 = f4z(), b4 = f4z(), g4 = f4z(), be4 = f4z();
        // oth: 2 -> 100
        if (act) { w0 = ld4(oW + j0); w1 = ld4(oW + HD + j0);
                   b4 = ld4(ob + j0); g4 = ld4(og + j0); be4 = ld4(obe + j0); }
        for (int n = 0; n < 15; n++) {
            float i0 = sw_[S_RAW + 52 + 2 * n], i1 = sw_[S_RAW + 52 + 2 * n + 1];
            float4 pre = f4z();
            if (act) {
                pre = fma4(i0, w0, fma4(i1, w1, b4));
                pre = tanh4(pre);
            }
            float4 o = ln4(pre, g4, be4, act);
            if (act) st4(sw_ + S_ENC + n * HD + j0, o);
        }
        // lm: 3 -> 100
        float4 w2 = f4z();
        if (act) { w0 = ld4(lW + j0); w1 = ld4(lW + HD + j0); w2 = ld4(lW + 2 * HD + j0);
                   b4 = ld4(lb + j0); g4 = ld4(lg + j0); be4 = ld4(lbe + j0); }
        for (int n = 0; n < 16; n++) {
            float i0 = sw_[S_RAW + 4 + 3 * n], i1 = sw_[S_RAW + 4 + 3 * n + 1], i2 = sw_[S_RAW + 4 + 3 * n + 2];
            float4 pre = f4z();
            if (act) {
                pre = fma4(i0, w0, fma4(i1, w1, fma4(i2, w2, b4)));
                pre = tanh4(pre);
            }
            float4 o = ln4(pre, g4, be4, act);
            if (act) st4(sw_ + S_ENC + (15 + n) * HD + j0, o);
        }
        // gl: 2 -> 100
        if (act) { w0 = ld4(gW + j0); w1 = ld4(gW + HD + j0);
                   b4 = ld4(gb + j0); g4 = ld4(gg + j0); be4 = ld4(gbe + j0); }
        for (int n = 0; n < 16; n++) {
            float i0 = sw_[S_RAW + 82 + 2 * n], i1 = sw_[S_RAW + 82 + 2 * n + 1];
            float4 pre = f4z();
            if (act) {
                pre = fma4(i0, w0, fma4(i1, w1, b4));
                pre = tanh4(pre);
            }
            float4 o = ln4(pre, g4, be4, act);
            if (act) st4(sw_ + S_ENC + (31 + n) * HD + j0, o);
        }
    }
    __syncwarp();

    // ---- fused 100x100 matvecs: qa = se@Ac, ql = se@Lc, gpre = se@fcW ----
    float4 qa = f4z(), ql = f4z(), gp = f4z();
    if (act) {
        gp = ld4(fcb + j0);
#pragma unroll 4
        for (int k = 0; k < HD; k++) {
            float s = sw_[S_SE + k];
            qa = fma4(s, ld4(Ac  + k * HD + j0), qa);
            ql = fma4(s, ld4(Lc  + k * HD + j0), ql);
            gp = fma4(s, ld4(fcW + k * HD + j0), gp);
        }
        gp = tanh4(gp);
    }
    // gi -> x[0:100]
    {
        float4 g4 = act ? ld4(fcg + j0) : f4z();
        float4 b4 = act ? ld4(fcbe + j0) : f4z();
        float4 gi = ln4(gp, g4, b4, act);
        if (act) st4(sw_ + S_X + j0, gi);
    }
    __syncwarp();

    // ---- attention heads ----
    attn_head(sw_, S_ENC + 0 * HD,  15, qa, sw_ + S_X + 100, act, lane, j0); // va (oth)
    attn_head(sw_, S_ENC + 15 * HD, 16, ql, sw_ + S_X + 200, act, lane, j0); // vl (lm)
    attn_head(sw_, S_ENC + 31 * HD, 16, ql, sw_ + S_X + 300, act, lane, j0); // vg (gl) — ql reused (source bug preserved)

    // ---- f1: 400 -> 100, tanh, LN ----
    {
        float4 acc = f4z();
        if (act) {
            acc = ld4(f1b + j0);
#pragma unroll 4
            for (int k = 0; k < 4 * HD; k++) {
                float s = sw_[S_X + k];
                acc = fma4(s, ld4(f1W + k * HD + j0), acc);
            }
            acc = tanh4(acc);
        }
        float4 g4 = act ? ld4(f1g + j0) : f4z();
        float4 b4 = act ? ld4(f1be + j0) : f4z();
        float4 h  = ln4(acc, g4, b4, act);
        if (act) st4(sw_ + S_H + j0, h);
    }
    __syncwarp();

    // ---- f2: 100 -> 100, tanh, LN -> output ----
    {
        float4 acc = f4z();
        if (act) {
            acc = ld4(f2b + j0);
#pragma unroll 4
            for (int k = 0; k < HD; k++) {
                float s = sw_[S_H + k];
                acc = fma4(s, ld4(f2W + k * HD + j0), acc);
            }
            acc = tanh4(acc);
        }
        float4 g4 = act ? ld4(f2g + j0) : f4z();
        float4 b4 = act ? ld4(f2be + j0) : f4z();
        float4 o  = ln4(acc, g4, b4, act);
        if (act) st4(out + (long)row * HD + j0, o);
    }
}

extern "C" void kernel_launch(void* const* d_in, const int* in_sizes, int n_in,
                              void* d_out, int out_size) {
    const float* inp = (const float*)d_in[0];
    const int B = in_sizes[0] / OBS;

    cudaFuncSetAttribute(obsenc_kernel, cudaFuncAttributeMaxDynamicSharedMemorySize, SMEM_BYTES);

    dim3 grid((B + RPB - 1) / RPB);
    obsenc_kernel<<<grid, RPB * 32, SMEM_BYTES>>>(
        inp, B,
        (const float*)d_in[2],  (const float*)d_in[3],  (const float*)d_in[4],  (const float*)d_in[5],
        (const float*)d_in[6],  (const float*)d_in[7],  (const float*)d_in[8],  (const float*)d_in[9],
        (const float*)d_in[10], (const float*)d_in[11], (const float*)d_in[12], (const float*)d_in[13],
        (const float*)d_in[14], (const float*)d_in[15], (const float*)d_in[16], (const float*)d_in[17],
        (const float*)d_in[18], (const float*)d_in[19],
        (const float*)d_in[20], (const float*)d_in[21], (const float*)d_in[22], (const float*)d_in[23],
        (const float*)d_in[24], (const float*)d_in[25], (const float*)d_in[26], (const float*)d_in[27],
        (const float*)d_in[28], (const float*)d_in[29], (const float*)d_in[30], (const float*)d_in[31],
        (float*)d_out);
}

// round 4
// speedup vs baseline: 2.1950x; 2.1950x over previous
#include <cuda_runtime.h>
#include <math.h>

#define HD   100
#define OBS  114
#define RPB  8          // warps per block
#define R    2          // rows per warp

// per-row smem layout (float offsets)
#define S_RAW 0         // 116 used
#define S_SE  120       // 100
#define S_X   220       // 400 (gi|va|vl|vg)
#define S_H   620       // 100
#define S_ST  720       // 32 (16 x float2 attn stats)
#define SROW  752       // floats per row (16B-aligned)
#define SMEM_BYTES (RPB * R * SROW * 4)

__device__ __forceinline__ float4 ld4(const float* p) { return *reinterpret_cast<const float4*>(p); }
__device__ __forceinline__ void   st4(float* p, float4 v) { *reinterpret_cast<float4*>(p) = v; }
__device__ __forceinline__ float4 f4z() { return make_float4(0.f, 0.f, 0.f, 0.f); }
__device__ __forceinline__ float4 fma4(float s, float4 w, float4 a) {
    a.x = fmaf(s, w.x, a.x); a.y = fmaf(s, w.y, a.y);
    a.z = fmaf(s, w.z, a.z); a.w = fmaf(s, w.w, a.w);
    return a;
}
__device__ __forceinline__ float hsum4(float4 v) { return (v.x + v.y) + (v.z + v.w); }
__device__ __forceinline__ float dot4(float4 a, float4 b) {
    return fmaf(a.x, b.x, fmaf(a.y, b.y, fmaf(a.z, b.z, a.w * b.w)));
}
__device__ __forceinline__ float wsum(float v) {
#pragma unroll
    for (int o = 16; o; o >>= 1) v += __shfl_xor_sync(0xffffffffu, v, o);
    return v;
}
__device__ __forceinline__ float wmax(float v) {
#pragma unroll
    for (int o = 16; o; o >>= 1) v = fmaxf(v, __shfl_xor_sync(0xffffffffu, v, o));
    return v;
}
__device__ __forceinline__ float ex2a(float x) { float y; asm("ex2.approx.f32 %0,%1;" : "=f"(y) : "f"(x)); return y; }
__device__ __forceinline__ float rcpa(float x) { float y; asm("rcp.approx.f32 %0,%1;" : "=f"(y) : "f"(x)); return y; }
// tanh(x) = sign(x) * (1 - e) / (1 + e),  e = exp(-2|x|)   (2 MUFU + few ALU, rel err ~1e-6)
__device__ __forceinline__ float tanhfast(float x) {
    float ax = fabsf(x);
    float e  = ex2a(ax * -2.8853900817779268f);
    float r  = (1.f - e) * rcpa(1.f + e);
    return copysignf(r, x);
}
__device__ __forceinline__ float4 tanh4f(float4 v) {
    v.x = tanhfast(v.x); v.y = tanhfast(v.y); v.z = tanhfast(v.z); v.w = tanhfast(v.w);
    return v;
}
// LayerNorm over 100 features on lanes 0..24 (4 each)
__device__ __forceinline__ float4 ln4(float4 pre, float4 g, float4 b, bool act) {
    float s  = act ? hsum4(pre) : 0.f;
    float sq = act ? dot4(pre, pre) : 0.f;
    s = wsum(s); sq = wsum(sq);
    float m = s * 0.01f;
    float r = rsqrtf(sq * 0.01f - m * m + 1e-5f);
    float4 o;
    o.x = (pre.x - m) * r * g.x + b.x;
    o.y = (pre.y - m) * r * g.y + b.y;
    o.z = (pre.z - m) * r * g.z + b.z;
    o.w = (pre.w - m) * r * g.w + b.w;
    return o;
}

// Recompute-style attention head over NN encoder instances with IN inputs each.
// Pass 1: per-n LN stats + logit via  logit = r*(sum(t*u) - m*U) + C,  u = g⊙q.
// Pass 2: recompute t_n, accumulate va = g*(sum c_n t_n - sum c_n m_n) + be,  c_n = alpha_n r_n.
template<int IN, int NN>
__device__ void attn_head(float* s0, float* s1, float4 q0, float4 q1, int rawOff,
                          const float* W, const float* Bv, const float* G, const float* BE,
                          int xoff, bool act, int lane, int j0)
{
    float4 w[IN], b4 = f4z(), g4 = f4z(), be4 = f4z();
#pragma unroll
    for (int i = 0; i < IN; i++) w[i] = f4z();
    if (act) {
#pragma unroll
        for (int i = 0; i < IN; i++) w[i] = ld4(W + i * HD + j0);
        b4 = ld4(Bv + j0); g4 = ld4(G + j0); be4 = ld4(BE + j0);
    }
    float4 u0 = make_float4(g4.x * q0.x, g4.y * q0.y, g4.z * q0.z, g4.w * q0.w);
    float4 u1 = make_float4(g4.x * q1.x, g4.y * q1.y, g4.z * q1.z, g4.w * q1.w);
    float U0 = wsum(hsum4(u0));
    float U1 = wsum(hsum4(u1));
    float C0 = wsum(dot4(q0, be4));
    float C1 = wsum(dot4(q1, be4));

    float mylog0 = 0.f, mym0 = 0.f, myr0 = 0.f;
    float mylog1 = 0.f, mym1 = 0.f, myr1 = 0.f;
    for (int n = 0; n < NN; n++) {
        float4 p0 = b4, p1 = b4;
#pragma unroll
        for (int i = 0; i < IN; i++) {
            p0 = fma4(s0[rawOff + IN * n + i], w[i], p0);
            p1 = fma4(s1[rawOff + IN * n + i], w[i], p1);
        }
        float4 t0 = tanh4f(p0), t1 = tanh4f(p1);
        // inactive lanes: w=b=g=0 -> t=0, u=0 -> zero contributions
        float a0 = wsum(hsum4(t0));
        float v0 = wsum(dot4(t0, t0));
        float d0 = wsum(dot4(t0, u0));
        float a1 = wsum(hsum4(t1));
        float v1 = wsum(dot4(t1, t1));
        float d1 = wsum(dot4(t1, u1));
        float m0 = a0 * 0.01f, m1 = a1 * 0.01f;
        float r0 = rsqrtf(v0 * 0.01f - m0 * m0 + 1e-5f);
        float r1 = rsqrtf(v1 * 0.01f - m1 * m1 + 1e-5f);
        float l0 = r0 * (d0 - m0 * U0) + C0;
        float l1 = r1 * (d1 - m1 * U1) + C1;
        if (lane == n) { mylog0 = l0; mym0 = m0; myr0 = r0;
                         mylog1 = l1; mym1 = m1; myr1 = r1; }
    }
    // softmax over lanes 0..NN-1
    const float LOG2E = 1.4426950408889634f;
    float mx0 = wmax(lane < NN ? mylog0 : -1e30f);
    float mx1 = wmax(lane < NN ? mylog1 : -1e30f);
    float e0 = lane < NN ? ex2a((mylog0 - mx0) * LOG2E) : 0.f;
    float e1 = lane < NN ? ex2a((mylog1 - mx1) * LOG2E) : 0.f;
    float den0 = wsum(e0), den1 = wsum(e1);
    if (lane < NN) {
        float c0 = e0 * rcpa(den0) * myr0;
        float c1 = e1 * rcpa(den1) * myr1;
        *reinterpret_cast<float2*>(s0 + S_ST + 2 * lane) = make_float2(mym0, c0);
        *reinterpret_cast<float2*>(s1 + S_ST + 2 * lane) = make_float2(mym1, c1);
    }
    __syncwarp();
    // pass 2: recompute encoders, weighted sum
    float4 A0 = f4z(), A1 = f4z();
    float K0 = 0.f, K1 = 0.f;
    for (int n = 0; n < NN; n++) {
        float2 st0 = *reinterpret_cast<const float2*>(s0 + S_ST + 2 * n);
        float2 st1 = *reinterpret_cast<const float2*>(s1 + S_ST + 2 * n);
        float4 p0 = b4, p1 = b4;
#pragma unroll
        for (int i = 0; i < IN; i++) {
            p0 = fma4(s0[rawOff + IN * n + i], w[i], p0);
            p1 = fma4(s1[rawOff + IN * n + i], w[i], p1);
        }
        float4 t0 = tanh4f(p0), t1 = tanh4f(p1);
        A0 = fma4(st0.y, t0, A0);
        A1 = fma4(st1.y, t1, A1);
        K0 = fmaf(st0.y, st0.x, K0);
        K1 = fmaf(st1.y, st1.x, K1);
    }
    if (act) {
        float4 o0, o1;
        o0.x = fmaf(g4.x, A0.x - K0, be4.x); o0.y = fmaf(g4.y, A0.y - K0, be4.y);
        o0.z = fmaf(g4.z, A0.z - K0, be4.z); o0.w = fmaf(g4.w, A0.w - K0, be4.w);
        o1.x = fmaf(g4.x, A1.x - K1, be4.x); o1.y = fmaf(g4.y, A1.y - K1, be4.y);
        o1.z = fmaf(g4.z, A1.z - K1, be4.z); o1.w = fmaf(g4.w, A1.w - K1, be4.w);
        st4(s0 + S_X + xoff + j0, o0);
        st4(s1 + S_X + xoff + j0, o1);
    }
    __syncwarp();
}

extern __shared__ float smem[];

__global__ void __launch_bounds__(RPB * 32, 2) obsenc_kernel(
    const float* __restrict__ inp, int B,
    const float* __restrict__ sW,  const float* __restrict__ sb,  const float* __restrict__ sg,  const float* __restrict__ sbe,
    const float* __restrict__ oW,  const float* __restrict__ ob,  const float* __restrict__ og,  const float* __restrict__ obe,
    const float* __restrict__ lW,  const float* __restrict__ lb,  const float* __restrict__ lg,  const float* __restrict__ lbe,
    const float* __restrict__ gW,  const float* __restrict__ gb,  const float* __restrict__ gg,  const float* __restrict__ gbe,
    const float* __restrict__ Ac,  const float* __restrict__ Lc,
    const float* __restrict__ fcW, const float* __restrict__ fcb, const float* __restrict__ fcg, const float* __restrict__ fcbe,
    const float* __restrict__ f1W, const float* __restrict__ f1b, const float* __restrict__ f1g, const float* __restrict__ f1be,
    const float* __restrict__ f2W, const float* __restrict__ f2b, const float* __restrict__ f2g, const float* __restrict__ f2be,
    float* __restrict__ out)
{
    const int warp = threadIdx.x >> 5;
    const int lane = threadIdx.x & 31;
    const int row0 = (blockIdx.x * RPB + warp) * R;
    if (row0 >= B) return;
    const int row1 = min(row0 + 1, B - 1);

    float* s0 = smem + (warp * R) * SROW;
    float* s1 = s0 + SROW;
    const bool act = lane < 25;
    const int  j0  = lane * 4;

    // ---- raw rows -> smem ----
    {
        const float* p0 = inp + (long)row0 * OBS;
        const float* p1 = inp + (long)row1 * OBS;
        for (int i = lane; i < OBS; i += 32) { s0[S_RAW + i] = p0[i]; s1[S_RAW + i] = p1[i]; }
    }
    __syncwarp();

    // ---- self encoder: 4 -> 100 ----
    {
        float4 w0 = f4z(), w1 = f4z(), w2 = f4z(), w3 = f4z(), b4 = f4z(), g4 = f4z(), be4 = f4z();
        if (act) {
            w0 = ld4(sW + j0); w1 = ld4(sW + HD + j0); w2 = ld4(sW + 2 * HD + j0); w3 = ld4(sW + 3 * HD + j0);
            b4 = ld4(sb + j0); g4 = ld4(sg + j0); be4 = ld4(sbe + j0);
        }
        float4 p0 = b4, p1 = b4;
        p0 = fma4(s0[S_RAW + 0], w0, p0); p0 = fma4(s0[S_RAW + 1], w1, p0);
        p0 = fma4(s0[S_RAW + 2], w2, p0); p0 = fma4(s0[S_RAW + 3], w3, p0);
        p1 = fma4(s1[S_RAW + 0], w0, p1); p1 = fma4(s1[S_RAW + 1], w1, p1);
        p1 = fma4(s1[S_RAW + 2], w2, p1); p1 = fma4(s1[S_RAW + 3], w3, p1);
        p0 = tanh4f(p0); p1 = tanh4f(p1);
        float4 e0 = ln4(p0, g4, be4, act), e1 = ln4(p1, g4, be4, act);
        if (act) { st4(s0 + S_SE + j0, e0); st4(s1 + S_SE + j0, e1); }
    }
    __syncwarp();

    // ---- fused 100x100 matvecs (row-pair blocked): qa, ql, gp ----
    float4 qa0 = f4z(), qa1 = f4z(), ql0 = f4z(), ql1 = f4z(), gp0 = f4z(), gp1 = f4z();
    if (act) {
        gp0 = ld4(fcb + j0); gp1 = gp0;
#pragma unroll 2
        for (int k = 0; k < HD; k++) {
            float4 wa = ld4(Ac + k * HD + j0);
            float4 wl = ld4(Lc + k * HD + j0);
            float4 wf = ld4(fcW + k * HD + j0);
            float x0 = s0[S_SE + k], x1 = s1[S_SE + k];
            qa0 = fma4(x0, wa, qa0); qa1 = fma4(x1, wa, qa1);
            ql0 = fma4(x0, wl, ql0); ql1 = fma4(x1, wl, ql1);
            gp0 = fma4(x0, wf, gp0); gp1 = fma4(x1, wf, gp1);
        }
        gp0 = tanh4f(gp0); gp1 = tanh4f(gp1);
    }
    {
        float4 g4 = f4z(), b4 = f4z();
        if (act) { g4 = ld4(fcg + j0); b4 = ld4(fcbe + j0); }
        float4 gi0 = ln4(gp0, g4, b4, act), gi1 = ln4(gp1, g4, b4, act);
        if (act) { st4(s0 + S_X + j0, gi0); st4(s1 + S_X + j0, gi1); }
    }
    __syncwarp();

    // ---- attention heads (ql reused for goal head: source bug preserved) ----
    attn_head<2, 15>(s0, s1, qa0, qa1, S_RAW + 52, oW, ob, og, obe, 100, act, lane, j0);
    attn_head<3, 16>(s0, s1, ql0, ql1, S_RAW + 4,  lW, lb, lg, lbe, 200, act, lane, j0);
    attn_head<2, 16>(s0, s1, ql0, ql1, S_RAW + 82, gW, gb, gg, gbe, 300, act, lane, j0);

    // ---- f1: 400 -> 100 (row-pair blocked) ----
    {
        float4 a0 = f4z(), a1 = f4z();
        if (act) {
            a0 = ld4(f1b + j0); a1 = a0;
#pragma unroll 4
            for (int k = 0; k < 4 * HD; k++) {
                float4 w = ld4(f1W + k * HD + j0);
                a0 = fma4(s0[S_X + k], w, a0);
                a1 = fma4(s1[S_X + k], w, a1);
            }
            a0 = tanh4f(a0); a1 = tanh4f(a1);
        }
        float4 g4 = f4z(), b4 = f4z();
        if (act) { g4 = ld4(f1g + j0); b4 = ld4(f1be + j0); }
        float4 h0 = ln4(a0, g4, b4, act), h1 = ln4(a1, g4, b4, act);
        if (act) { st4(s0 + S_H + j0, h0); st4(s1 + S_H + j0, h1); }
    }
    __syncwarp();

    // ---- f2: 100 -> 100 -> out ----
    {
        float4 a0 = f4z(), a1 = f4z();
        if (act) {
            a0 = ld4(f2b + j0); a1 = a0;
#pragma unroll 4
            for (int k = 0; k < HD; k++) {
                float4 w = ld4(f2W + k * HD + j0);
                a0 = fma4(s0[S_H + k], w, a0);
                a1 = fma4(s1[S_H + k], w, a1);
            }
            a0 = tanh4f(a0); a1 = tanh4f(a1);
        }
        float4 g4 = f4z(), b4 = f4z();
        if (act) { g4 = ld4(f2g + j0); b4 = ld4(f2be + j0); }
        float4 o0 = ln4(a0, g4, b4, act), o1 = ln4(a1, g4, b4, act);
        if (act) {
            st4(out + (long)row0 * HD + j0, o0);
            st4(out + (long)row1 * HD + j0, o1);
        }
    }
}

extern "C" void kernel_launch(void* const* d_in, const int* in_sizes, int n_in,
                              void* d_out, int out_size) {
    const float* inp = (const float*)d_in[0];
    const int B = in_sizes[0] / OBS;

    cudaFuncSetAttribute(obsenc_kernel, cudaFuncAttributeMaxDynamicSharedMemorySize, SMEM_BYTES);

    const int rowsPerBlock = RPB * R;
    dim3 grid((B + rowsPerBlock - 1) / rowsPerBlock);
    obsenc_kernel<<<grid, RPB * 32, SMEM_BYTES>>>(
        inp, B,
        (const float*)d_in[2],  (const float*)d_in[3],  (const float*)d_in[4],  (const float*)d_in[5],
        (const float*)d_in[6],  (const float*)d_in[7],  (const float*)d_in[8],  (const float*)d_in[9],
        (const float*)d_in[10], (const float*)d_in[11], (const float*)d_in[12], (const float*)d_in[13],
        (const float*)d_in[14], (const float*)d_in[15], (const float*)d_in[16], (const float*)d_in[17],
        (const float*)d_in[18], (const float*)d_in[19],
        (const float*)d_in[20], (const float*)d_in[21], (const float*)d_in[22], (const float*)d_in[23],
        (const float*)d_in[24], (const float*)d_in[25], (const float*)d_in[26], (const float*)d_in[27],
        (const float*)d_in[28], (const float*)d_in[29], (const float*)d_in[30], (const float*)d_in[31],
        (float*)d_out);
}

// round 7
// speedup vs baseline: 3.0575x; 1.3930x over previous
#include <cuda_runtime.h>
#include <math.h>

#define HD   100
#define OBS  114
#define RPB  8          // warps per block
#define R    4          // rows per warp

// per-row smem layout (float offsets)
#define S_RAW 0         // 116 used
#define S_SE  120       // 100
#define S_X   220       // 400 (gi|va|vl|vg)
#define S_H   620       // 100
#define S_ST  720       // 32 (16 x float2 attn stats)
#define SROW  752       // floats per row (16B-aligned)
#define SMEM_BYTES (RPB * R * SROW * 4)

typedef unsigned long long u64;
struct pf4 { u64 a, b; };   // packed f32x2 pair = 4 floats

__device__ __forceinline__ float4 ld4(const float* p) { return *reinterpret_cast<const float4*>(p); }
__device__ __forceinline__ void   st4(float* p, float4 v) { *reinterpret_cast<float4*>(p) = v; }
__device__ __forceinline__ float4 f4z() { return make_float4(0.f, 0.f, 0.f, 0.f); }
__device__ __forceinline__ pf4    pz()  { pf4 r; r.a = 0ull; r.b = 0ull; return r; }
__device__ __forceinline__ pf4 ldp(const float* p) {
    ulonglong2 v = *reinterpret_cast<const ulonglong2*>(p);
    pf4 r; r.a = v.x; r.b = v.y; return r;
}
__device__ __forceinline__ u64 pk(float s) {
    u64 d; asm("mov.b64 %0,{%1,%1};" : "=l"(d) : "f"(s)); return d;
}
__device__ __forceinline__ void fmap(u64 s, const pf4& w, pf4& acc) {
    asm("fma.rn.f32x2 %0,%2,%3,%0;\n\t"
        "fma.rn.f32x2 %1,%2,%4,%1;"
        : "+l"(acc.a), "+l"(acc.b) : "l"(s), "l"(w.a), "l"(w.b));
}
__device__ __forceinline__ float4 upk(const pf4& p) {
    float4 v;
    asm("mov.b64 {%0,%1},%2;" : "=f"(v.x), "=f"(v.y) : "l"(p.a));
    asm("mov.b64 {%0,%1},%2;" : "=f"(v.z), "=f"(v.w) : "l"(p.b));
    return v;
}
__device__ __forceinline__ float getc(float4 v, int k) {
    return k == 0 ? v.x : (k == 1 ? v.y : (k == 2 ? v.z : v.w));
}
__device__ __forceinline__ float4 fma4(float s, float4 w, float4 a) {
    a.x = fmaf(s, w.x, a.x); a.y = fmaf(s, w.y, a.y);
    a.z = fmaf(s, w.z, a.z); a.w = fmaf(s, w.w, a.w);
    return a;
}
__device__ __forceinline__ float hsum4(float4 v) { return (v.x + v.y) + (v.z + v.w); }
__device__ __forceinline__ float dot4(float4 a, float4 b) {
    return fmaf(a.x, b.x, fmaf(a.y, b.y, fmaf(a.z, b.z, a.w * b.w)));
}
// butterfly warp reductions (redux.sync.f32 does NOT exist on sm_103)
__device__ __forceinline__ float wsum(float v) {
#pragma unroll
    for (int o = 16; o; o >>= 1) v += __shfl_xor_sync(0xffffffffu, v, o);
    return v;
}
__device__ __forceinline__ float wmax(float v) {
#pragma unroll
    for (int o = 16; o; o >>= 1) v = fmaxf(v, __shfl_xor_sync(0xffffffffu, v, o));
    return v;
}
__device__ __forceinline__ float ex2a(float x) { float y; asm("ex2.approx.f32 %0,%1;" : "=f"(y) : "f"(x)); return y; }
__device__ __forceinline__ float rcpa(float x) { float y; asm("rcp.approx.f32 %0,%1;" : "=f"(y) : "f"(x)); return y; }
// tanh(x) = 1 - 2/(1 + e^{2x}); saturates correctly at +-inf, no sign handling (5 instr)
__device__ __forceinline__ float tanhf5(float x) {
    float e = ex2a(x * 2.8853900817779268f);   // 2*log2(e)
    return fmaf(-2.f, rcpa(1.f + e), 1.f);
}
__device__ __forceinline__ float4 tanh4f(float4 v) {
    v.x = tanhf5(v.x); v.y = tanhf5(v.y); v.z = tanhf5(v.z); v.w = tanhf5(v.w);
    return v;
}
// LayerNorm over 100 features on lanes 0..24 (4 each)
__device__ __forceinline__ float4 ln4(float4 pre, float4 g, float4 b, bool act) {
    float s  = act ? hsum4(pre) : 0.f;
    float sq = act ? dot4(pre, pre) : 0.f;
    s = wsum(s); sq = wsum(sq);
    float m = s * 0.01f;
    float r = rsqrtf(sq * 0.01f - m * m + 1e-5f);
    float4 o;
    o.x = (pre.x - m) * r * g.x + b.x;
    o.y = (pre.y - m) * r * g.y + b.y;
    o.z = (pre.z - m) * r * g.z + b.z;
    o.w = (pre.w - m) * r * g.w + b.w;
    return o;
}

// Recompute-style attention head (2 rows), packed-FMA encoder recompute.
template<int IN, int NN>
__device__ void attn_head(float* s0, float* s1, float4 q0, float4 q1, int rawOff,
                          const float* W, const float* Bv, const float* G, const float* BE,
                          int xoff, bool act, int lane, int j0)
{
    pf4 w[IN], bp = pz();
    float4 g4 = f4z(), be4 = f4z();
#pragma unroll
    for (int i = 0; i < IN; i++) w[i] = pz();
    if (act) {
#pragma unroll
        for (int i = 0; i < IN; i++) w[i] = ldp(W + i * HD + j0);
        bp = ldp(Bv + j0); g4 = ld4(G + j0); be4 = ld4(BE + j0);
    }
    float4 u0 = make_float4(g4.x * q0.x, g4.y * q0.y, g4.z * q0.z, g4.w * q0.w);
    float4 u1 = make_float4(g4.x * q1.x, g4.y * q1.y, g4.z * q1.z, g4.w * q1.w);
    float U0 = wsum(hsum4(u0));
    float U1 = wsum(hsum4(u1));
    float C0 = wsum(dot4(q0, be4));
    float C1 = wsum(dot4(q1, be4));

    float mylog0 = 0.f, mym0 = 0.f, myr0 = 0.f;
    float mylog1 = 0.f, mym1 = 0.f, myr1 = 0.f;
    for (int n = 0; n < NN; n++) {
        pf4 p0 = bp, p1 = bp;
#pragma unroll
        for (int i = 0; i < IN; i++) {
            fmap(pk(s0[rawOff + IN * n + i]), w[i], p0);
            fmap(pk(s1[rawOff + IN * n + i]), w[i], p1);
        }
        float4 t0 = tanh4f(upk(p0)), t1 = tanh4f(upk(p1));
        // inactive lanes: w=b=0 -> p=0 -> t=0 -> zero contributions
        float a0 = wsum(hsum4(t0));
        float v0 = wsum(dot4(t0, t0));
        float d0 = wsum(dot4(t0, u0));
        float a1 = wsum(hsum4(t1));
        float v1 = wsum(dot4(t1, t1));
        float d1 = wsum(dot4(t1, u1));
        float m0 = a0 * 0.01f, m1 = a1 * 0.01f;
        float r0 = rsqrtf(v0 * 0.01f - m0 * m0 + 1e-5f);
        float r1 = rsqrtf(v1 * 0.01f - m1 * m1 + 1e-5f);
        float l0 = fmaf(r0, d0 - m0 * U0, C0);
        float l1 = fmaf(r1, d1 - m1 * U1, C1);
        if (lane == n) { mylog0 = l0; mym0 = m0; myr0 = r0;
                         mylog1 = l1; mym1 = m1; myr1 = r1; }
    }
    // softmax over lanes 0..NN-1
    const float LOG2E = 1.4426950408889634f;
    float mx0 = wmax(lane < NN ? mylog0 : -1e30f);
    float mx1 = wmax(lane < NN ? mylog1 : -1e30f);
    float e0 = lane < NN ? ex2a((mylog0 - mx0) * LOG2E) : 0.f;
    float e1 = lane < NN ? ex2a((mylog1 - mx1) * LOG2E) : 0.f;
    float den0 = wsum(e0), den1 = wsum(e1);
    if (lane < NN) {
        float c0 = e0 * rcpa(den0) * myr0;
        float c1 = e1 * rcpa(den1) * myr1;
        *reinterpret_cast<float2*>(s0 + S_ST + 2 * lane) = make_float2(mym0, c0);
        *reinterpret_cast<float2*>(s1 + S_ST + 2 * lane) = make_float2(mym1, c1);
    }
    __syncwarp();
    // pass 2: recompute encoders, weighted sum
    float4 A0 = f4z(), A1 = f4z();
    float K0 = 0.f, K1 = 0.f;
    for (int n = 0; n < NN; n++) {
        float2 st0 = *reinterpret_cast<const float2*>(s0 + S_ST + 2 * n);
        float2 st1 = *reinterpret_cast<const float2*>(s1 + S_ST + 2 * n);
        pf4 p0 = bp, p1 = bp;
#pragma unroll
        for (int i = 0; i < IN; i++) {
            fmap(pk(s0[rawOff + IN * n + i]), w[i], p0);
            fmap(pk(s1[rawOff + IN * n + i]), w[i], p1);
        }
        float4 t0 = tanh4f(upk(p0)), t1 = tanh4f(upk(p1));
        A0 = fma4(st0.y, t0, A0);
        A1 = fma4(st1.y, t1, A1);
        K0 = fmaf(st0.y, st0.x, K0);
        K1 = fmaf(st1.y, st1.x, K1);
    }
    if (act) {
        float4 o0, o1;
        o0.x = fmaf(g4.x, A0.x - K0, be4.x); o0.y = fmaf(g4.y, A0.y - K0, be4.y);
        o0.z = fmaf(g4.z, A0.z - K0, be4.z); o0.w = fmaf(g4.w, A0.w - K0, be4.w);
        o1.x = fmaf(g4.x, A1.x - K1, be4.x); o1.y = fmaf(g4.y, A1.y - K1, be4.y);
        o1.z = fmaf(g4.z, A1.z - K1, be4.z); o1.w = fmaf(g4.w, A1.w - K1, be4.w);
        st4(s0 + S_X + xoff + j0, o0);
        st4(s1 + S_X + xoff + j0, o1);
    }
    __syncwarp();
}

extern __shared__ float smem[];

__global__ void __launch_bounds__(RPB * 32, 2) obsenc_kernel(
    const float* __restrict__ inp, int B,
    const float* __restrict__ sW,  const float* __restrict__ sb,  const float* __restrict__ sg,  const float* __restrict__ sbe,
    const float* __restrict__ oW,  const float* __restrict__ ob,  const float* __restrict__ og,  const float* __restrict__ obe,
    const float* __restrict__ lW,  const float* __restrict__ lb,  const float* __restrict__ lg,  const float* __restrict__ lbe,
    const float* __restrict__ gW,  const float* __restrict__ gb,  const float* __restrict__ gg,  const float* __restrict__ gbe,
    const float* __restrict__ Ac,  const float* __restrict__ Lc,
    const float* __restrict__ fcW, const float* __restrict__ fcb, const float* __restrict__ fcg, const float* __restrict__ fcbe,
    const float* __restrict__ f1W, const float* __restrict__ f1b, const float* __restrict__ f1g, const float* __restrict__ f1be,
    const float* __restrict__ f2W, const float* __restrict__ f2b, const float* __restrict__ f2g, const float* __restrict__ f2be,
    float* __restrict__ out)
{
    const int warp = threadIdx.x >> 5;
    const int lane = threadIdx.x & 31;
    const int row0 = (blockIdx.x * RPB + warp) * R;
    if (row0 >= B) return;

    float* s[R];
    int rows[R];
#pragma unroll
    for (int r = 0; r < R; r++) {
        rows[r] = min(row0 + r, B - 1);
        s[r] = smem + (warp * R + r) * SROW;
    }
    const bool act = lane < 25;
    const int  j0  = lane * 4;

    // ---- raw rows -> smem ----
#pragma unroll
    for (int r = 0; r < R; r++) {
        const float* p = inp + (long)rows[r] * OBS;
        for (int i = lane; i < OBS; i += 32) s[r][S_RAW + i] = p[i];
    }
    __syncwarp();

    // ---- self encoder: 4 -> 100 ----
    {
        pf4 w0 = pz(), w1 = pz(), w2 = pz(), w3 = pz(), bp = pz();
        float4 g4 = f4z(), be4 = f4z();
        if (act) {
            w0 = ldp(sW + j0); w1 = ldp(sW + HD + j0); w2 = ldp(sW + 2 * HD + j0); w3 = ldp(sW + 3 * HD + j0);
            bp = ldp(sb + j0); g4 = ld4(sg + j0); be4 = ld4(sbe + j0);
        }
#pragma unroll
        for (int r = 0; r < R; r++) {
            pf4 p = bp;
            fmap(pk(s[r][S_RAW + 0]), w0, p);
            fmap(pk(s[r][S_RAW + 1]), w1, p);
            fmap(pk(s[r][S_RAW + 2]), w2, p);
            fmap(pk(s[r][S_RAW + 3]), w3, p);
            float4 e = ln4(tanh4f(upk(p)), g4, be4, act);
            if (act) st4(s[r] + S_SE + j0, e);
        }
    }
    __syncwarp();

    // ---- fused 100x100 matvecs (4-row blocked, packed): qa = se@Ac, ql = se@Lc ----
    pf4 qa[R], ql[R];
#pragma unroll
    for (int r = 0; r < R; r++) { qa[r] = pz(); ql[r] = pz(); }
    if (act) {
#pragma unroll 2
        for (int k4 = 0; k4 < 25; k4++) {
            float4 xv[R];
#pragma unroll
            for (int r = 0; r < R; r++) xv[r] = ld4(s[r] + S_SE + 4 * k4);
#pragma unroll
            for (int kk = 0; kk < 4; kk++) {
                const int k = 4 * k4 + kk;
                pf4 wa = ldp(Ac + k * HD + j0);
                pf4 wl = ldp(Lc + k * HD + j0);
#pragma unroll
                for (int r = 0; r < R; r++) {
                    u64 xs = pk(getc(xv[r], kk));
                    fmap(xs, wa, qa[r]);
                    fmap(xs, wl, ql[r]);
                }
            }
        }
    }
    // ---- fc: gi = LN(tanh(se@fcW + fcb)) -> x[0:100] ----
    {
        pf4 gp[R];
#pragma unroll
        for (int r = 0; r < R; r++) gp[r] = pz();
        if (act) {
            pf4 bp = ldp(fcb + j0);
#pragma unroll
            for (int r = 0; r < R; r++) gp[r] = bp;
#pragma unroll 2
            for (int k4 = 0; k4 < 25; k4++) {
                float4 xv[R];
#pragma unroll
                for (int r = 0; r < R; r++) xv[r] = ld4(s[r] + S_SE + 4 * k4);
#pragma unroll
                for (int kk = 0; kk < 4; kk++) {
                    pf4 wf = ldp(fcW + (4 * k4 + kk) * HD + j0);
#pragma unroll
                    for (int r = 0; r < R; r++) fmap(pk(getc(xv[r], kk)), wf, gp[r]);
                }
            }
        }
        float4 g4 = f4z(), b4 = f4z();
        if (act) { g4 = ld4(fcg + j0); b4 = ld4(fcbe + j0); }
#pragma unroll
        for (int r = 0; r < R; r++) {
            float4 gi = ln4(tanh4f(upk(gp[r])), g4, b4, act);
            if (act) st4(s[r] + S_X + j0, gi);
        }
    }
    __syncwarp();

    // ---- attention heads (2 rows per call to bound registers) ----
    {
        float4 qaF[R], qlF[R];
#pragma unroll
        for (int r = 0; r < R; r++) { qaF[r] = upk(qa[r]); qlF[r] = upk(ql[r]); }
        attn_head<2, 15>(s[0], s[1], qaF[0], qaF[1], S_RAW + 52, oW, ob, og, obe, 100, act, lane, j0);
        attn_head<2, 15>(s[2], s[3], qaF[2], qaF[3], S_RAW + 52, oW, ob, og, obe, 100, act, lane, j0);
        attn_head<3, 16>(s[0], s[1], qlF[0], qlF[1], S_RAW + 4,  lW, lb, lg, lbe, 200, act, lane, j0);
        attn_head<3, 16>(s[2], s[3], qlF[2], qlF[3], S_RAW + 4,  lW, lb, lg, lbe, 200, act, lane, j0);
        attn_head<2, 16>(s[0], s[1], qlF[0], qlF[1], S_RAW + 82, gW, gb, gg, gbe, 300, act, lane, j0);
        attn_head<2, 16>(s[2], s[3], qlF[2], qlF[3], S_RAW + 82, gW, gb, gg, gbe, 300, act, lane, j0);
    }

    // ---- f1: 400 -> 100 (4-row blocked, packed) ----
    {
        pf4 a[R];
#pragma unroll
        for (int r = 0; r < R; r++) a[r] = pz();
        if (act) {
            pf4 bp = ldp(f1b + j0);
#pragma unroll
            for (int r = 0; r < R; r++) a[r] = bp;
#pragma unroll 2
            for (int k4 = 0; k4 < 100; k4++) {
                float4 xv[R];
#pragma unroll
                for (int r = 0; r < R; r++) xv[r] = ld4(s[r] + S_X + 4 * k4);
#pragma unroll
                for (int kk = 0; kk < 4; kk++) {
                    pf4 w = ldp(f1W + (4 * k4 + kk) * HD + j0);
#pragma unroll
                    for (int r = 0; r < R; r++) fmap(pk(getc(xv[r], kk)), w, a[r]);
                }
            }
        }
        float4 g4 = f4z(), b4 = f4z();
        if (act) { g4 = ld4(f1g + j0); b4 = ld4(f1be + j0); }
#pragma unroll
        for (int r = 0; r < R; r++) {
            float4 h = ln4(tanh4f(upk(a[r])), g4, b4, act);
            if (act) st4(s[r] + S_H + j0, h);
        }
    }
    __syncwarp();

    // ---- f2: 100 -> 100 -> out ----
    {
        pf4 a[R];
#pragma unroll
        for (int r = 0; r < R; r++) a[r] = pz();
        if (act) {
            pf4 bp = ldp(f2b + j0);
#pragma unroll
            for (int r = 0; r < R; r++) a[r] = bp;
#pragma unroll 2
            for (int k4 = 0; k4 < 25; k4++) {
                float4 xv[R];
#pragma unroll
                for (int r = 0; r < R; r++) xv[r] = ld4(s[r] + S_H + 4 * k4);
#pragma unroll
                for (int kk = 0; kk < 4; kk++) {
                    pf4 w = ldp(f2W + (4 * k4 + kk) * HD + j0);
#pragma unroll
                    for (int r = 0; r < R; r++) fmap(pk(getc(xv[r], kk)), w, a[r]);
                }
            }
        }
        float4 g4 = f4z(), b4 = f4z();
        if (act) { g4 = ld4(f2g + j0); b4 = ld4(f2be + j0); }
#pragma unroll
        for (int r = 0; r < R; r++) {
            float4 o = ln4(tanh4f(upk(a[r])), g4, b4, act);
            if (act) st4(out + (long)rows[r] * HD + j0, o);
        }
    }
}

extern "C" void kernel_launch(void* const* d_in, const int* in_sizes, int n_in,
                              void* d_out, int out_size) {
    const float* inp = (const float*)d_in[0];
    const int B = in_sizes[0] / OBS;

    cudaFuncSetAttribute(obsenc_kernel, cudaFuncAttributeMaxDynamicSharedMemorySize, SMEM_BYTES);

    const int rowsPerBlock = RPB * R;
    dim3 grid((B + rowsPerBlock - 1) / rowsPerBlock);
    obsenc_kernel<<<grid, RPB * 32, SMEM_BYTES>>>(
        inp, B,
        (const float*)d_in[2],  (const float*)d_in[3],  (const float*)d_in[4],  (const float*)d_in[5],
        (const float*)d_in[6],  (const float*)d_in[7],  (const float*)d_in[8],  (const float*)d_in[9],
        (const float*)d_in[10], (const float*)d_in[11], (const float*)d_in[12], (const float*)d_in[13],
        (const float*)d_in[14], (const float*)d_in[15], (const float*)d_in[16], (const float*)d_in[17],
        (const float*)d_in[18], (const float*)d_in[19],
        (const float*)d_in[20], (const float*)d_in[21], (const float*)d_in[22], (const float*)d_in[23],
        (const float*)d_in[24], (const float*)d_in[25], (const float*)d_in[26], (const float*)d_in[27],
        (const float*)d_in[28], (const float*)d_in[29], (const float*)d_in[30], (const float*)d_in[31],
        (float*)d_out);
}

// round 8
// speedup vs baseline: 3.5806x; 1.1711x over previous
#include <cuda_runtime.h>
#include <math.h>

#define HD   100
#define OBS  114
#define RPB  8          // warps per block
#define R    4          // rows per warp

// block-shared packed attention weight tables (float offsets in smem)
#define TB_O  0         // oth: 100 x float4 (w0,w1,b,g)
#define TB_L  400       // lm : 100 x float4 (w0,w1,w2,b)
#define TB_G  800       // gl : 100 x float4 (w0,w1,b,g)
#define TB_LG 1200      // lm gamma: 100 floats
#define RBASE 1312      // per-row regions start (16B aligned)

// per-row smem layout (float offsets)
#define S_RAW 0         // 116 used
#define S_SE  120       // 100 (self-emb, then reused as q store during attention, dead after)
#define S_X   220       // 400 (gi|va|vl|vg)
#define S_H   620       // 100
#define S_ST  720       // 32 (16 x float2 attn stats)
#define SROW  752       // floats per row (16B-aligned)
#define SMEM_BYTES ((RBASE + RPB * R * SROW) * 4)

typedef unsigned long long u64;
struct pf4 { u64 a, b; };   // packed f32x2 pair = 4 floats

__device__ __forceinline__ float4 ld4(const float* p) { return *reinterpret_cast<const float4*>(p); }
__device__ __forceinline__ void   st4(float* p, float4 v) { *reinterpret_cast<float4*>(p) = v; }
__device__ __forceinline__ float4 f4z() { return make_float4(0.f, 0.f, 0.f, 0.f); }
__device__ __forceinline__ pf4    pz()  { pf4 r; r.a = 0ull; r.b = 0ull; return r; }
__device__ __forceinline__ pf4 ldp(const float* p) {
    ulonglong2 v = *reinterpret_cast<const ulonglong2*>(p);
    pf4 r; r.a = v.x; r.b = v.y; return r;
}
__device__ __forceinline__ u64 pk(float s) {
    u64 d; asm("mov.b64 %0,{%1,%1};" : "=l"(d) : "f"(s)); return d;
}
__device__ __forceinline__ void fmap(u64 s, const pf4& w, pf4& acc) {
    asm("fma.rn.f32x2 %0,%2,%3,%0;\n\t"
        "fma.rn.f32x2 %1,%2,%4,%1;"
        : "+l"(acc.a), "+l"(acc.b) : "l"(s), "l"(w.a), "l"(w.b));
}
__device__ __forceinline__ float4 upk(const pf4& p) {
    float4 v;
    asm("mov.b64 {%0,%1},%2;" : "=f"(v.x), "=f"(v.y) : "l"(p.a));
    asm("mov.b64 {%0,%1},%2;" : "=f"(v.z), "=f"(v.w) : "l"(p.b));
    return v;
}
__device__ __forceinline__ float getc(float4 v, int k) {
    return k == 0 ? v.x : (k == 1 ? v.y : (k == 2 ? v.z : v.w));
}
__device__ __forceinline__ float4 fma4(float s, float4 w, float4 a) {
    a.x = fmaf(s, w.x, a.x); a.y = fmaf(s, w.y, a.y);
    a.z = fmaf(s, w.z, a.z); a.w = fmaf(s, w.w, a.w);
    return a;
}
__device__ __forceinline__ float hsum4(float4 v) { return (v.x + v.y) + (v.z + v.w); }
__device__ __forceinline__ float dot4(float4 a, float4 b) {
    return fmaf(a.x, b.x, fmaf(a.y, b.y, fmaf(a.z, b.z, a.w * b.w)));
}
// butterfly warp reductions (redux.sync.f32 does NOT exist on sm_103)
__device__ __forceinline__ float wsum(float v) {
#pragma unroll
    for (int o = 16; o; o >>= 1) v += __shfl_xor_sync(0xffffffffu, v, o);
    return v;
}
__device__ __forceinline__ float ex2a(float x) { float y; asm("ex2.approx.f32 %0,%1;" : "=f"(y) : "f"(x)); return y; }
__device__ __forceinline__ float rcpa(float x) { float y; asm("rcp.approx.f32 %0,%1;" : "=f"(y) : "f"(x)); return y; }
// tanh(x) = 1 - 2/(1 + e^{2x}); saturates correctly at +-inf (5 instr)
__device__ __forceinline__ float tanhf5(float x) {
    float e = ex2a(x * 2.8853900817779268f);   // 2*log2(e)
    return fmaf(-2.f, rcpa(1.f + e), 1.f);
}
__device__ __forceinline__ float4 tanh4f(float4 v) {
    v.x = tanhf5(v.x); v.y = tanhf5(v.y); v.z = tanhf5(v.z); v.w = tanhf5(v.w);
    return v;
}
// LayerNorm over 100 features on lanes 0..24 (4 each)
__device__ __forceinline__ float4 ln4(float4 pre, float4 g, float4 b, bool act) {
    float s  = act ? hsum4(pre) : 0.f;
    float sq = act ? dot4(pre, pre) : 0.f;
    s = wsum(s); sq = wsum(sq);
    float m = s * 0.01f;
    float r = rsqrtf(sq * 0.01f - m * m + 1e-5f);
    float4 o;
    o.x = (pre.x - m) * r * g.x + b.x;
    o.y = (pre.y - m) * r * g.y + b.y;
    o.z = (pre.z - m) * r * g.z + b.z;
    o.w = (pre.w - m) * r * g.w + b.w;
    return o;
}

// Attention head, 2 rows.
// Pass 1 TRANSPOSED: lane = encoder instance (lanes 0..15 -> row0, 16..31 -> row1);
//   each lane walks j=0..99 with in-lane stats -> logit, zero warp reductions.
//   logit = r*(sum_j t_j*g_j*q_j - m*U) + C,  U = sum g_j q_j, C = sum be_j q_j.
// Softmax per 16-lane group. Pass 2 in j-layout recomputes t and accumulates.
template<int IN, int NN>
__device__ void attn_head(float* s0, float* s1, const float* tbl, const float* tblg,
                          float4 q0, float4 q1, int rawOff,
                          const float* W, const float* Bv, const float* G, const float* BE,
                          int xoff, bool act, int lane, int j0, bool storeQ)
{
    // ---- j-layout prep: weights for pass 2, U/C, stash q in dead S_SE region ----
    pf4 w[IN], bp = pz();
    float4 g4 = f4z(), be4 = f4z();
#pragma unroll
    for (int i = 0; i < IN; i++) w[i] = pz();
    if (act) {
#pragma unroll
        for (int i = 0; i < IN; i++) w[i] = ldp(W + i * HD + j0);
        bp = ldp(Bv + j0); g4 = ld4(G + j0); be4 = ld4(BE + j0);
        if (storeQ) { st4(s0 + S_SE + j0, q0); st4(s1 + S_SE + j0, q1); }
    }
    float4 u0 = make_float4(g4.x * q0.x, g4.y * q0.y, g4.z * q0.z, g4.w * q0.w);
    float4 u1 = make_float4(g4.x * q1.x, g4.y * q1.y, g4.z * q1.z, g4.w * q1.w);
    float U0 = wsum(hsum4(u0));
    float U1 = wsum(hsum4(u1));
    float C0 = wsum(dot4(q0, be4));
    float C1 = wsum(dot4(q1, be4));
    __syncwarp();   // q stores visible before transposed reads

    // ---- pass 1 transposed ----
    {
        const int gn = lane & 15;
        float* bs = (lane < 16) ? s0 : s1;
        const float Uq = (lane < 16) ? U0 : U1;
        const float Cq = (lane < 16) ? C0 : C1;
        float iv[IN];
#pragma unroll
        for (int i = 0; i < IN; i++) iv[i] = bs[rawOff + IN * gn + i];
        float a = 0.f, vv = 0.f, d = 0.f;
#pragma unroll 4
        for (int j = 0; j < HD; j++) {
            float4 T = ld4(tbl + 4 * j);
            float qj = bs[S_SE + j];
            float p, gj;
            if (IN == 2) { p = fmaf(iv[0], T.x, fmaf(iv[1], T.y, T.z)); gj = T.w; }
            else         { p = fmaf(iv[0], T.x, fmaf(iv[1], T.y, fmaf(iv[2], T.z, T.w))); gj = tblg[j]; }
            float t = tanhf5(p);
            a += t;
            vv = fmaf(t, t, vv);
            d  = fmaf(gj * qj, t, d);
        }
        float m = a * 0.01f;
        float r = rsqrtf(vv * 0.01f - m * m + 1e-5f);
        float l = (gn < NN) ? fmaf(r, d - m * Uq, Cq) : -1e30f;
        // softmax within each 16-lane group (xor offsets < 16 stay in-half)
        const float LOG2E = 1.4426950408889634f;
        float mx = l;
#pragma unroll
        for (int o = 8; o; o >>= 1) mx = fmaxf(mx, __shfl_xor_sync(0xffffffffu, mx, o));
        float e = (gn < NN) ? ex2a((l - mx) * LOG2E) : 0.f;
        float den = e;
#pragma unroll
        for (int o = 8; o; o >>= 1) den += __shfl_xor_sync(0xffffffffu, den, o);
        if (gn < NN) {
            float c = e * rcpa(den) * r;
            *reinterpret_cast<float2*>(bs + S_ST + 2 * gn) = make_float2(m, c);
        }
    }
    __syncwarp();

    // ---- pass 2: j-layout recompute + weighted accumulate ----
    float4 A0 = f4z(), A1 = f4z();
    float K0 = 0.f, K1 = 0.f;
    for (int n = 0; n < NN; n++) {
        float2 st0 = *reinterpret_cast<const float2*>(s0 + S_ST + 2 * n);
        float2 st1 = *reinterpret_cast<const float2*>(s1 + S_ST + 2 * n);
        pf4 p0 = bp, p1 = bp;
#pragma unroll
        for (int i = 0; i < IN; i++) {
            fmap(pk(s0[rawOff + IN * n + i]), w[i], p0);
            fmap(pk(s1[rawOff + IN * n + i]), w[i], p1);
        }
        float4 t0 = tanh4f(upk(p0)), t1 = tanh4f(upk(p1));
        A0 = fma4(st0.y, t0, A0);
        A1 = fma4(st1.y, t1, A1);
        K0 = fmaf(st0.y, st0.x, K0);
        K1 = fmaf(st1.y, st1.x, K1);
    }
    if (act) {
        float4 o0, o1;
        o0.x = fmaf(g4.x, A0.x - K0, be4.x); o0.y = fmaf(g4.y, A0.y - K0, be4.y);
        o0.z = fmaf(g4.z, A0.z - K0, be4.z); o0.w = fmaf(g4.w, A0.w - K0, be4.w);
        o1.x = fmaf(g4.x, A1.x - K1, be4.x); o1.y = fmaf(g4.y, A1.y - K1, be4.y);
        o1.z = fmaf(g4.z, A1.z - K1, be4.z); o1.w = fmaf(g4.w, A1.w - K1, be4.w);
        st4(s0 + S_X + xoff + j0, o0);
        st4(s1 + S_X + xoff + j0, o1);
    }
    __syncwarp();
}

extern __shared__ float smem[];

__global__ void __launch_bounds__(RPB * 32, 2) obsenc_kernel(
    const float* __restrict__ inp, int B,
    const float* __restrict__ sW,  const float* __restrict__ sb,  const float* __restrict__ sg,  const float* __restrict__ sbe,
    const float* __restrict__ oW,  const float* __restrict__ ob,  const float* __restrict__ og,  const float* __restrict__ obe,
    const float* __restrict__ lW,  const float* __restrict__ lb,  const float* __restrict__ lg,  const float* __restrict__ lbe,
    const float* __restrict__ gW,  const float* __restrict__ gb,  const float* __restrict__ gg,  const float* __restrict__ gbe,
    const float* __restrict__ Ac,  const float* __restrict__ Lc,
    const float* __restrict__ fcW, const float* __restrict__ fcb, const float* __restrict__ fcg, const float* __restrict__ fcbe,
    const float* __restrict__ f1W, const float* __restrict__ f1b, const float* __restrict__ f1g, const float* __restrict__ f1be,
    const float* __restrict__ f2W, const float* __restrict__ f2b, const float* __restrict__ f2g, const float* __restrict__ f2be,
    float* __restrict__ out)
{
    // ---- stage packed attention weight tables (block-shared) ----
    for (int j = threadIdx.x; j < HD; j += RPB * 32) {
        st4(smem + TB_O + 4 * j, make_float4(oW[j], oW[HD + j], ob[j], og[j]));
        st4(smem + TB_L + 4 * j, make_float4(lW[j], lW[HD + j], lW[2 * HD + j], lb[j]));
        st4(smem + TB_G + 4 * j, make_float4(gW[j], gW[HD + j], gb[j], gg[j]));
        smem[TB_LG + j] = lg[j];
    }
    __syncthreads();

    const int warp = threadIdx.x >> 5;
    const int lane = threadIdx.x & 31;
    const int row0 = (blockIdx.x * RPB + warp) * R;
    if (row0 >= B) return;

    float* s[R];
    int rows[R];
#pragma unroll
    for (int r = 0; r < R; r++) {
        rows[r] = min(row0 + r, B - 1);
        s[r] = smem + RBASE + (warp * R + r) * SROW;
    }
    const bool act = lane < 25;
    const int  j0  = lane * 4;

    // ---- raw rows -> smem ----
#pragma unroll
    for (int r = 0; r < R; r++) {
        const float* p = inp + (long)rows[r] * OBS;
        for (int i = lane; i < OBS; i += 32) s[r][S_RAW + i] = p[i];
    }
    __syncwarp();

    // ---- self encoder: 4 -> 100 ----
    {
        pf4 w0 = pz(), w1 = pz(), w2 = pz(), w3 = pz(), bp = pz();
        float4 g4 = f4z(), be4 = f4z();
        if (act) {
            w0 = ldp(sW + j0); w1 = ldp(sW + HD + j0); w2 = ldp(sW + 2 * HD + j0); w3 = ldp(sW + 3 * HD + j0);
            bp = ldp(sb + j0); g4 = ld4(sg + j0); be4 = ld4(sbe + j0);
        }
#pragma unroll
        for (int r = 0; r < R; r++) {
            pf4 p = bp;
            fmap(pk(s[r][S_RAW + 0]), w0, p);
            fmap(pk(s[r][S_RAW + 1]), w1, p);
            fmap(pk(s[r][S_RAW + 2]), w2, p);
            fmap(pk(s[r][S_RAW + 3]), w3, p);
            float4 e = ln4(tanh4f(upk(p)), g4, be4, act);
            if (act) st4(s[r] + S_SE + j0, e);
        }
    }
    __syncwarp();

    // ---- fused 100x100 matvecs (4-row blocked, packed): qa = se@Ac, ql = se@Lc ----
    pf4 qa[R], ql[R];
#pragma unroll
    for (int r = 0; r < R; r++) { qa[r] = pz(); ql[r] = pz(); }
    if (act) {
#pragma unroll 2
        for (int k4 = 0; k4 < 25; k4++) {
            float4 xv[R];
#pragma unroll
            for (int r = 0; r < R; r++) xv[r] = ld4(s[r] + S_SE + 4 * k4);
#pragma unroll
            for (int kk = 0; kk < 4; kk++) {
                const int k = 4 * k4 + kk;
                pf4 wa = ldp(Ac + k * HD + j0);
                pf4 wl = ldp(Lc + k * HD + j0);
#pragma unroll
                for (int r = 0; r < R; r++) {
                    u64 xs = pk(getc(xv[r], kk));
                    fmap(xs, wa, qa[r]);
                    fmap(xs, wl, ql[r]);
                }
            }
        }
    }
    // ---- fc: gi = LN(tanh(se@fcW + fcb)) -> x[0:100] ----
    {
        pf4 gp[R];
#pragma unroll
        for (int r = 0; r < R; r++) gp[r] = pz();
        if (act) {
            pf4 bp = ldp(fcb + j0);
#pragma unroll
            for (int r = 0; r < R; r++) gp[r] = bp;
#pragma unroll 2
            for (int k4 = 0; k4 < 25; k4++) {
                float4 xv[R];
#pragma unroll
                for (int r = 0; r < R; r++) xv[r] = ld4(s[r] + S_SE + 4 * k4);
#pragma unroll
                for (int kk = 0; kk < 4; kk++) {
                    pf4 wf = ldp(fcW + (4 * k4 + kk) * HD + j0);
#pragma unroll
                    for (int r = 0; r < R; r++) fmap(pk(getc(xv[r], kk)), wf, gp[r]);
                }
            }
        }
        float4 g4 = f4z(), b4 = f4z();
        if (act) { g4 = ld4(fcg + j0); b4 = ld4(fcbe + j0); }
#pragma unroll
        for (int r = 0; r < R; r++) {
            float4 gi = ln4(tanh4f(upk(gp[r])), g4, b4, act);
            if (act) st4(s[r] + S_X + j0, gi);
        }
    }
    __syncwarp();

    // ---- attention heads (2 rows per call; ql reused for goal head: source bug preserved) ----
    {
        float4 qaF[R], qlF[R];
#pragma unroll
        for (int r = 0; r < R; r++) { qaF[r] = upk(qa[r]); qlF[r] = upk(ql[r]); }
        attn_head<2, 15>(s[0], s[1], smem + TB_O, nullptr,   qaF[0], qaF[1], S_RAW + 52, oW, ob, og, obe, 100, act, lane, j0, true);
        attn_head<2, 15>(s[2], s[3], smem + TB_O, nullptr,   qaF[2], qaF[3], S_RAW + 52, oW, ob, og, obe, 100, act, lane, j0, true);
        attn_head<3, 16>(s[0], s[1], smem + TB_L, smem + TB_LG, qlF[0], qlF[1], S_RAW + 4, lW, lb, lg, lbe, 200, act, lane, j0, true);
        attn_head<3, 16>(s[2], s[3], smem + TB_L, smem + TB_LG, qlF[2], qlF[3], S_RAW + 4, lW, lb, lg, lbe, 200, act, lane, j0, true);
        attn_head<2, 16>(s[0], s[1], smem + TB_G, nullptr,   qlF[0], qlF[1], S_RAW + 82, gW, gb, gg, gbe, 300, act, lane, j0, false);
        attn_head<2, 16>(s[2], s[3], smem + TB_G, nullptr,   qlF[2], qlF[3], S_RAW + 82, gW, gb, gg, gbe, 300, act, lane, j0, false);
    }

    // ---- f1: 400 -> 100 (4-row blocked, packed) ----
    {
        pf4 a[R];
#pragma unroll
        for (int r = 0; r < R; r++) a[r] = pz();
        if (act) {
            pf4 bp = ldp(f1b + j0);
#pragma unroll
            for (int r = 0; r < R; r++) a[r] = bp;
#pragma unroll 2
            for (int k4 = 0; k4 < 100; k4++) {
                float4 xv[R];
#pragma unroll
                for (int r = 0; r < R; r++) xv[r] = ld4(s[r] + S_X + 4 * k4);
#pragma unroll
                for (int kk = 0; kk < 4; kk++) {
                    pf4 w = ldp(f1W + (4 * k4 + kk) * HD + j0);
#pragma unroll
                    for (int r = 0; r < R; r++) fmap(pk(getc(xv[r], kk)), w, a[r]);
                }
            }
        }
        float4 g4 = f4z(), b4 = f4z();
        if (act) { g4 = ld4(f1g + j0); b4 = ld4(f1be + j0); }
#pragma unroll
        for (int r = 0; r < R; r++) {
            float4 h = ln4(tanh4f(upk(a[r])), g4, b4, act);
            if (act) st4(s[r] + S_H + j0, h);
        }
    }
    __syncwarp();

    // ---- f2: 100 -> 100 -> out ----
    {
        pf4 a[R];
#pragma unroll
        for (int r = 0; r < R; r++) a[r] = pz();
        if (act) {
            pf4 bp = ldp(f2b + j0);
#pragma unroll
            for (int r = 0; r < R; r++) a[r] = bp;
#pragma unroll 2
            for (int k4 = 0; k4 < 25; k4++) {
                float4 xv[R];
#pragma unroll
                for (int r = 0; r < R; r++) xv[r] = ld4(s[r] + S_H + 4 * k4);
#pragma unroll
                for (int kk = 0; kk < 4; kk++) {
                    pf4 w = ldp(f2W + (4 * k4 + kk) * HD + j0);
#pragma unroll
                    for (int r = 0; r < R; r++) fmap(pk(getc(xv[r], kk)), w, a[r]);
                }
            }
        }
        float4 g4 = f4z(), b4 = f4z();
        if (act) { g4 = ld4(f2g + j0); b4 = ld4(f2be + j0); }
#pragma unroll
        for (int r = 0; r < R; r++) {
            float4 o = ln4(tanh4f(upk(a[r])), g4, b4, act);
            if (act) st4(out + (long)rows[r] * HD + j0, o);
        }
    }
}

extern "C" void kernel_launch(void* const* d_in, const int* in_sizes, int n_in,
                              void* d_out, int out_size) {
    const float* inp = (const float*)d_in[0];
    const int B = in_sizes[0] / OBS;

    cudaFuncSetAttribute(obsenc_kernel, cudaFuncAttributeMaxDynamicSharedMemorySize, SMEM_BYTES);

    const int rowsPerBlock = RPB * R;
    dim3 grid((B + rowsPerBlock - 1) / rowsPerBlock);
    obsenc_kernel<<<grid, RPB * 32, SMEM_BYTES>>>(
        inp, B,
        (const float*)d_in[2],  (const float*)d_in[3],  (const float*)d_in[4],  (const float*)d_in[5],
        (const float*)d_in[6],  (const float*)d_in[7],  (const float*)d_in[8],  (const float*)d_in[9],
        (const float*)d_in[10], (const float*)d_in[11], (const float*)d_in[12], (const float*)d_in[13],
        (const float*)d_in[14], (const float*)d_in[15], (const float*)d_in[16], (const float*)d_in[17],
        (const float*)d_in[18], (const float*)d_in[19],
        (const float*)d_in[20], (const float*)d_in[21], (const float*)d_in[22], (const float*)d_in[23],
        (const float*)d_in[24], (const float*)d_in[25], (const float*)d_in[26], (const float*)d_in[27],
        (const float*)d_in[28], (const float*)d_in[29], (const float*)d_in[30], (const float*)d_in[31],
        (float*)d_out);
}

// round 10
// speedup vs baseline: 3.7423x; 1.0451x over previous
#include <cuda_runtime.h>
#include <math.h>

#define HD   100
#define OBS  114
#define RPB  8          // warps per block
#define R    4          // rows per warp
#define C2L  2.8853900817779268f   // 2*log2(e)

// block-shared packed attention weight tables (float offsets in smem), pre-scaled by C2L
#define TB_O  0         // oth: 100 x float4 (c*w0, c*w1, c*b, -)
#define TB_L  400       // lm : 100 x float4 (c*w0, c*w1, c*w2, c*b)
#define TB_G  800       // gl : 100 x float4 (c*w0, c*w1, c*b, -)
#define RBASE 1200      // per-row regions start (16B aligned)

// per-row smem layout (float offsets)
#define S_RAW 0         // 116 used
#define S_SE  120       // 100 (self-emb; u = g*q store during attention; dead after)
#define S_X   220       // 400 (gi|va|vl|vg)
#define S_H   620       // 100
#define S_ST  720       // 32 (16 x float2 attn stats)
#define SROW  752       // floats per row (16B-aligned)
#define SMEM_BYTES ((RBASE + RPB * R * SROW) * 4)

typedef unsigned long long u64;
struct pf4 { u64 a, b; };   // packed f32x2 pair = 4 floats

// pre-scaled weight copies (written by repack kernel; static device mem, no allocation)
__device__ float g_sW [4 * HD];
__device__ float g_fcW[HD * HD];
__device__ float g_f1W[4 * HD * HD];
__device__ float g_f2W[HD * HD];

__global__ void repack_kernel(const float* __restrict__ sW, const float* __restrict__ fcW,
                              const float* __restrict__ f1W, const float* __restrict__ f2W) {
    int i = blockIdx.x * blockDim.x + threadIdx.x;
    if (i < 4 * HD)      g_sW[i]  = sW[i]  * C2L;
    if (i < HD * HD)     g_fcW[i] = fcW[i] * C2L;
    if (i < HD * HD)     g_f2W[i] = f2W[i] * C2L;
    if (i < 4 * HD * HD) g_f1W[i] = f1W[i] * C2L;
}

__device__ __forceinline__ float4 ld4(const float* p) { return *reinterpret_cast<const float4*>(p); }
__device__ __forceinline__ void   st4(float* p, float4 v) { *reinterpret_cast<float4*>(p) = v; }
__device__ __forceinline__ float4 f4z() { return make_float4(0.f, 0.f, 0.f, 0.f); }
__device__ __forceinline__ pf4    pz()  { pf4 r; r.a = 0ull; r.b = 0ull; return r; }
__device__ __forceinline__ pf4 ldp(const float* p) {
    ulonglong2 v = *reinterpret_cast<const ulonglong2*>(p);
    pf4 r; r.a = v.x; r.b = v.y; return r;
}
__device__ __forceinline__ u64 pk(float s) {
    u64 d; asm("mov.b64 %0,{%1,%1};" : "=l"(d) : "f"(s)); return d;
}
__device__ __forceinline__ void fmap(u64 s, const pf4& w, pf4& acc) {
    asm("fma.rn.f32x2 %0,%2,%3,%0;\n\t"
        "fma.rn.f32x2 %1,%2,%4,%1;"
        : "+l"(acc.a), "+l"(acc.b) : "l"(s), "l"(w.a), "l"(w.b));
}
__device__ __forceinline__ pf4 sclp(pf4 p, u64 c) {
    asm("mul.rn.f32x2 %0,%0,%2;\n\t"
        "mul.rn.f32x2 %1,%1,%2;"
        : "+l"(p.a), "+l"(p.b) : "l"(c));
    return p;
}
__device__ __forceinline__ float4 upk(const pf4& p) {
    float4 v;
    asm("mov.b64 {%0,%1},%2;" : "=f"(v.x), "=f"(v.y) : "l"(p.a));
    asm("mov.b64 {%0,%1},%2;" : "=f"(v.z), "=f"(v.w) : "l"(p.b));
    return v;
}
__device__ __forceinline__ float getc(float4 v, int k) {
    return k == 0 ? v.x : (k == 1 ? v.y : (k == 2 ? v.z : v.w));
}
__device__ __forceinline__ float4 fma4(float s, float4 w, float4 a) {
    a.x = fmaf(s, w.x, a.x); a.y = fmaf(s, w.y, a.y);
    a.z = fmaf(s, w.z, a.z); a.w = fmaf(s, w.w, a.w);
    return a;
}
__device__ __forceinline__ float hsum4(float4 v) { return (v.x + v.y) + (v.z + v.w); }
__device__ __forceinline__ float dot4(float4 a, float4 b) {
    return fmaf(a.x, b.x, fmaf(a.y, b.y, fmaf(a.z, b.z, a.w * b.w)));
}
// butterfly warp reductions (redux.sync.f32 does NOT exist on sm_103)
__device__ __forceinline__ float wsum(float v) {
#pragma unroll
    for (int o = 16; o; o >>= 1) v += __shfl_xor_sync(0xffffffffu, v, o);
    return v;
}
__device__ __forceinline__ float ex2a(float x) { float y; asm("ex2.approx.f32 %0,%1;" : "=f"(y) : "f"(x)); return y; }
__device__ __forceinline__ float rcpa(float x) { float y; asm("rcp.approx.f32 %0,%1;" : "=f"(y) : "f"(x)); return y; }
// tanh of pre-scaled input: ps = 2*log2(e)*x -> tanh(x) = 1 - 2/(1 + 2^ps)  (4 instr)
__device__ __forceinline__ float tanhp(float ps) {
    float e = ex2a(ps);
    return fmaf(-2.f, rcpa(1.f + e), 1.f);
}
__device__ __forceinline__ float4 tanh4p(float4 v) {
    v.x = tanhp(v.x); v.y = tanhp(v.y); v.z = tanhp(v.z); v.w = tanhp(v.w);
    return v;
}
// LayerNorm over 100 features on lanes 0..24 (4 each)
__device__ __forceinline__ float4 ln4(float4 pre, float4 g, float4 b, bool act) {
    float s  = act ? hsum4(pre) : 0.f;
    float sq = act ? dot4(pre, pre) : 0.f;
    s = wsum(s); sq = wsum(sq);
    float m = s * 0.01f;
    float r = rsqrtf(sq * 0.01f - m * m + 1e-5f);
    float4 o;
    o.x = (pre.x - m) * r * g.x + b.x;
    o.y = (pre.y - m) * r * g.y + b.y;
    o.z = (pre.z - m) * r * g.z + b.z;
    o.w = (pre.w - m) * r * g.w + b.w;
    return o;
}

// Attention head, 2 rows.
// Pass 1 TRANSPOSED: lane = encoder instance (lanes 0..15 -> row0, 16..31 -> row1);
//   each lane walks j=0..99 with in-lane stats -> logit, zero warp reductions.
//   u_j = g_j*q_j stored in S_SE; logit = r*(sum_j t_j*u_j - m*U) + C,  U = sum u_j, C = sum be_j*q_j.
// Softmax per 16-lane group. Pass 2 in j-layout recomputes t and accumulates.
template<int IN, int NN>
__device__ void attn_head(float* s0, float* s1, const float* tbl,
                          float4 q0, float4 q1, int rawOff,
                          const float* W, const float* Bv, const float* G, const float* BE,
                          int xoff, bool act, int lane, int j0)
{
    // ---- j-layout prep: pre-scaled weights for pass 2, U/C, u -> S_SE ----
    const u64 cc = pk(C2L);
    pf4 w[IN], bp = pz();
    float4 g4 = f4z(), be4 = f4z();
#pragma unroll
    for (int i = 0; i < IN; i++) w[i] = pz();
    float4 u0 = f4z(), u1 = f4z();
    if (act) {
#pragma unroll
        for (int i = 0; i < IN; i++) w[i] = sclp(ldp(W + i * HD + j0), cc);
        bp = sclp(ldp(Bv + j0), cc);
        g4 = ld4(G + j0); be4 = ld4(BE + j0);
        u0 = make_float4(g4.x * q0.x, g4.y * q0.y, g4.z * q0.z, g4.w * q0.w);
        u1 = make_float4(g4.x * q1.x, g4.y * q1.y, g4.z * q1.z, g4.w * q1.w);
        st4(s0 + S_SE + j0, u0); st4(s1 + S_SE + j0, u1);
    }
    float U0 = wsum(hsum4(u0));
    float U1 = wsum(hsum4(u1));
    float C0 = wsum(dot4(q0, be4));
    float C1 = wsum(dot4(q1, be4));
    __syncwarp();   // u stores visible before transposed reads

    // ---- pass 1 transposed ----
    {
        const int gn = lane & 15;
        float* bs = (lane < 16) ? s0 : s1;
        const float Uq = (lane < 16) ? U0 : U1;
        const float Cq = (lane < 16) ? C0 : C1;
        float iv[IN];
#pragma unroll
        for (int i = 0; i < IN; i++) iv[i] = bs[rawOff + IN * gn + i];
        float a = 0.f, vv = 0.f, d = 0.f;
#pragma unroll 4
        for (int j = 0; j < HD; j++) {
            float4 T = ld4(tbl + 4 * j);
            float uj = bs[S_SE + j];
            float ps;
            if (IN == 2) ps = fmaf(iv[0], T.x, fmaf(iv[1], T.y, T.z));
            else         ps = fmaf(iv[0], T.x, fmaf(iv[1], T.y, fmaf(iv[2], T.z, T.w)));
            float t = tanhp(ps);
            a += t;
            vv = fmaf(t, t, vv);
            d  = fmaf(uj, t, d);
        }
        float m = a * 0.01f;
        float r = rsqrtf(vv * 0.01f - m * m + 1e-5f);
        float l = (gn < NN) ? fmaf(r, d - m * Uq, Cq) : -1e30f;
        // softmax within each 16-lane group (xor offsets < 16 stay in-half)
        const float LOG2E = 1.4426950408889634f;
        float mx = l;
#pragma unroll
        for (int o = 8; o; o >>= 1) mx = fmaxf(mx, __shfl_xor_sync(0xffffffffu, mx, o));
        float e = (gn < NN) ? ex2a((l - mx) * LOG2E) : 0.f;
        float den = e;
#pragma unroll
        for (int o = 8; o; o >>= 1) den += __shfl_xor_sync(0xffffffffu, den, o);
        if (gn < NN) {
            float c = e * rcpa(den) * r;
            *reinterpret_cast<float2*>(bs + S_ST + 2 * gn) = make_float2(m, c);
        }
    }
    __syncwarp();

    // ---- pass 2: j-layout recompute + weighted accumulate ----
    float4 A0 = f4z(), A1 = f4z();
    float K0 = 0.f, K1 = 0.f;
    for (int n = 0; n < NN; n++) {
        float2 st0 = *reinterpret_cast<const float2*>(s0 + S_ST + 2 * n);
        float2 st1 = *reinterpret_cast<const float2*>(s1 + S_ST + 2 * n);
        pf4 p0 = bp, p1 = bp;
#pragma unroll
        for (int i = 0; i < IN; i++) {
            fmap(pk(s0[rawOff + IN * n + i]), w[i], p0);
            fmap(pk(s1[rawOff + IN * n + i]), w[i], p1);
        }
        float4 t0 = tanh4p(upk(p0)), t1 = tanh4p(upk(p1));
        A0 = fma4(st0.y, t0, A0);
        A1 = fma4(st1.y, t1, A1);
        K0 = fmaf(st0.y, st0.x, K0);
        K1 = fmaf(st1.y, st1.x, K1);
    }
    if (act) {
        float4 o0, o1;
        o0.x = fmaf(g4.x, A0.x - K0, be4.x); o0.y = fmaf(g4.y, A0.y - K0, be4.y);
        o0.z = fmaf(g4.z, A0.z - K0, be4.z); o0.w = fmaf(g4.w, A0.w - K0, be4.w);
        o1.x = fmaf(g4.x, A1.x - K1, be4.x); o1.y = fmaf(g4.y, A1.y - K1, be4.y);
        o1.z = fmaf(g4.z, A1.z - K1, be4.z); o1.w = fmaf(g4.w, A1.w - K1, be4.w);
        st4(s0 + S_X + xoff + j0, o0);
        st4(s1 + S_X + xoff + j0, o1);
    }
    __syncwarp();
}

extern __shared__ float smem[];

__global__ void __launch_bounds__(RPB * 32, 2) obsenc_kernel(
    const float* __restrict__ inp, int B,
    const float* __restrict__ sb,  const float* __restrict__ sg,  const float* __restrict__ sbe,
    const float* __restrict__ oW,  const float* __restrict__ ob,  const float* __restrict__ og,  const float* __restrict__ obe,
    const float* __restrict__ lW,  const float* __restrict__ lb,  const float* __restrict__ lg,  const float* __restrict__ lbe,
    const float* __restrict__ gW,  const float* __restrict__ gb,  const float* __restrict__ gg,  const float* __restrict__ gbe,
    const float* __restrict__ Ac,  const float* __restrict__ Lc,
    const float* __restrict__ fcb, const float* __restrict__ fcg, const float* __restrict__ fcbe,
    const float* __restrict__ f1b, const float* __restrict__ f1g, const float* __restrict__ f1be,
    const float* __restrict__ f2b, const float* __restrict__ f2g, const float* __restrict__ f2be,
    float* __restrict__ out)
{
    const u64 cc = pk(C2L);

    // ---- stage packed attention weight tables (block-shared, pre-scaled by C2L) ----
    for (int j = threadIdx.x; j < HD; j += RPB * 32) {
        st4(smem + TB_O + 4 * j, make_float4(oW[j] * C2L, oW[HD + j] * C2L, ob[j] * C2L, 0.f));
        st4(smem + TB_L + 4 * j, make_float4(lW[j] * C2L, lW[HD + j] * C2L, lW[2 * HD + j] * C2L, lb[j] * C2L));
        st4(smem + TB_G + 4 * j, make_float4(gW[j] * C2L, gW[HD + j] * C2L, gb[j] * C2L, 0.f));
    }
    __syncthreads();

    const int warp = threadIdx.x >> 5;
    const int lane = threadIdx.x & 31;
    const int row0 = (blockIdx.x * RPB + warp) * R;
    if (row0 >= B) return;

    float* s[R];
    int rows[R];
#pragma unroll
    for (int r = 0; r < R; r++) {
        rows[r] = min(row0 + r, B - 1);
        s[r] = smem + RBASE + (warp * R + r) * SROW;
    }
    const bool act = lane < 25;
    const int  j0  = lane * 4;

    // ---- raw rows -> smem ----
#pragma unroll
    for (int r = 0; r < R; r++) {
        const float* p = inp + (long)rows[r] * OBS;
        for (int i = lane; i < OBS; i += 32) s[r][S_RAW + i] = p[i];
    }
    __syncwarp();

    // ---- self encoder: 4 -> 100 (g_sW pre-scaled; bias scaled inline) ----
    {
        pf4 w0 = pz(), w1 = pz(), w2 = pz(), w3 = pz(), bp = pz();
        float4 g4 = f4z(), be4 = f4z();
        if (act) {
            w0 = ldp(g_sW + j0); w1 = ldp(g_sW + HD + j0); w2 = ldp(g_sW + 2 * HD + j0); w3 = ldp(g_sW + 3 * HD + j0);
            bp = sclp(ldp(sb + j0), cc);
            g4 = ld4(sg + j0); be4 = ld4(sbe + j0);
        }
#pragma unroll
        for (int r = 0; r < R; r++) {
            pf4 p = bp;
            fmap(pk(s[r][S_RAW + 0]), w0, p);
            fmap(pk(s[r][S_RAW + 1]), w1, p);
            fmap(pk(s[r][S_RAW + 2]), w2, p);
            fmap(pk(s[r][S_RAW + 3]), w3, p);
            float4 e = ln4(tanh4p(upk(p)), g4, be4, act);
            if (act) st4(s[r] + S_SE + j0, e);
        }
    }
    __syncwarp();

    // ---- fused 100x100 matvecs (4-row blocked, packed): qa = se@Ac, ql = se@Lc, gp = se@fcW' ----
    pf4 qa[R], ql[R], gp[R];
#pragma unroll
    for (int r = 0; r < R; r++) { qa[r] = pz(); ql[r] = pz(); gp[r] = pz(); }
    if (act) {
        pf4 bpfc = sclp(ldp(fcb + j0), cc);
#pragma unroll
        for (int r = 0; r < R; r++) gp[r] = bpfc;
#pragma unroll 2
        for (int k4 = 0; k4 < 25; k4++) {
            float4 xv[R];
#pragma unroll
            for (int r = 0; r < R; r++) xv[r] = ld4(s[r] + S_SE + 4 * k4);
#pragma unroll
            for (int kk = 0; kk < 4; kk++) {
                const int k = 4 * k4 + kk;
                pf4 wa = ldp(Ac + k * HD + j0);
                pf4 wl = ldp(Lc + k * HD + j0);
                pf4 wf = ldp(g_fcW + k * HD + j0);
#pragma unroll
                for (int r = 0; r < R; r++) {
                    u64 xs = pk(getc(xv[r], kk));
                    fmap(xs, wa, qa[r]);
                    fmap(xs, wl, ql[r]);
                    fmap(xs, wf, gp[r]);
                }
            }
        }
    }
    // gi -> x[0:100]
    {
        float4 g4 = f4z(), b4 = f4z();
        if (act) { g4 = ld4(fcg + j0); b4 = ld4(fcbe + j0); }
#pragma unroll
        for (int r = 0; r < R; r++) {
            float4 gi = ln4(tanh4p(upk(gp[r])), g4, b4, act);
            if (act) st4(s[r] + S_X + j0, gi);
        }
    }
    __syncwarp();

    // ---- attention heads (2 rows per call; ql reused for goal head: source bug preserved) ----
    {
        float4 qaF[R], qlF[R];
#pragma unroll
        for (int r = 0; r < R; r++) { qaF[r] = upk(qa[r]); qlF[r] = upk(ql[r]); }
        attn_head<2, 15>(s[0], s[1], smem + TB_O, qaF[0], qaF[1], S_RAW + 52, oW, ob, og, obe, 100, act, lane, j0);
        attn_head<2, 15>(s[2], s[3], smem + TB_O, qaF[2], qaF[3], S_RAW + 52, oW, ob, og, obe, 100, act, lane, j0);
        attn_head<3, 16>(s[0], s[1], smem + TB_L, qlF[0], qlF[1], S_RAW + 4,  lW, lb, lg, lbe, 200, act, lane, j0);
        attn_head<3, 16>(s[2], s[3], smem + TB_L, qlF[2], qlF[3], S_RAW + 4,  lW, lb, lg, lbe, 200, act, lane, j0);
        attn_head<2, 16>(s[0], s[1], smem + TB_G, qlF[0], qlF[1], S_RAW + 82, gW, gb, gg, gbe, 300, act, lane, j0);
        attn_head<2, 16>(s[2], s[3], smem + TB_G, qlF[2], qlF[3], S_RAW + 82, gW, gb, gg, gbe, 300, act, lane, j0);
    }

    // ---- f1: 400 -> 100 (4-row blocked, packed, g_f1W pre-scaled) ----
    {
        pf4 a[R];
#pragma unroll
        for (int r = 0; r < R; r++) a[r] = pz();
        if (act) {
            pf4 bp = sclp(ldp(f1b + j0), cc);
#pragma unroll
            for (int r = 0; r < R; r++) a[r] = bp;
#pragma unroll 2
            for (int k4 = 0; k4 < 100; k4++) {
                float4 xv[R];
#pragma unroll
                for (int r = 0; r < R; r++) xv[r] = ld4(s[r] + S_X + 4 * k4);
#pragma unroll
                for (int kk = 0; kk < 4; kk++) {
                    pf4 w = ldp(g_f1W + (4 * k4 + kk) * HD + j0);
#pragma unroll
                    for (int r = 0; r < R; r++) fmap(pk(getc(xv[r], kk)), w, a[r]);
                }
            }
        }
        float4 g4 = f4z(), b4 = f4z();
        if (act) { g4 = ld4(f1g + j0); b4 = ld4(f1be + j0); }
#pragma unroll
        for (int r = 0; r < R; r++) {
            float4 h = ln4(tanh4p(upk(a[r])), g4, b4, act);
            if (act) st4(s[r] + S_H + j0, h);
        }
    }
    __syncwarp();

    // ---- f2: 100 -> 100 -> out (g_f2W pre-scaled) ----
    {
        pf4 a[R];
#pragma unroll
        for (int r = 0; r < R; r++) a[r] = pz();
        if (act) {
            pf4 bp = sclp(ldp(f2b + j0), cc);
#pragma unroll
            for (int r = 0; r < R; r++) a[r] = bp;
#pragma unroll 2
            for (int k4 = 0; k4 < 25; k4++) {
                float4 xv[R];
#pragma unroll
                for (int r = 0; r < R; r++) xv[r] = ld4(s[r] + S_H + 4 * k4);
#pragma unroll
                for (int kk = 0; kk < 4; kk++) {
                    pf4 w = ldp(g_f2W + (4 * k4 + kk) * HD + j0);
#pragma unroll
                    for (int r = 0; r < R; r++) fmap(pk(getc(xv[r], kk)), w, a[r]);
                }
            }
        }
        float4 g4 = f4z(), b4 = f4z();
        if (act) { g4 = ld4(f2g + j0); b4 = ld4(f2be + j0); }
#pragma unroll
        for (int r = 0; r < R; r++) {
            float4 o = ln4(tanh4p(upk(a[r])), g4, b4, act);
            if (act) st4(out + (long)rows[r] * HD + j0, o);
        }
    }
}

extern "C" void kernel_launch(void* const* d_in, const int* in_sizes, int n_in,
                              void* d_out, int out_size) {
    const float* inp = (const float*)d_in[0];
    const int B = in_sizes[0] / OBS;

    // pre-scale tanh-feeding weights by 2*log2(e) into __device__ arrays
    repack_kernel<<<(4 * HD * HD + 255) / 256, 256>>>(
        (const float*)d_in[2], (const float*)d_in[20],
        (const float*)d_in[24], (const float*)d_in[28]);

    cudaFuncSetAttribute(obsenc_kernel, cudaFuncAttributeMaxDynamicSharedMemorySize, SMEM_BYTES);

    const int rowsPerBlock = RPB * R;
    dim3 grid((B + rowsPerBlock - 1) / rowsPerBlock);
    obsenc_kernel<<<grid, RPB * 32, SMEM_BYTES>>>(
        inp, B,
        (const float*)d_in[3],  (const float*)d_in[4],  (const float*)d_in[5],
        (const float*)d_in[6],  (const float*)d_in[7],  (const float*)d_in[8],  (const float*)d_in[9],
        (const float*)d_in[10], (const float*)d_in[11], (const float*)d_in[12], (const float*)d_in[13],
        (const float*)d_in[14], (const float*)d_in[15], (const float*)d_in[16], (const float*)d_in[17],
        (const float*)d_in[18], (const float*)d_in[19],
        (const float*)d_in[21], (const float*)d_in[22], (const float*)d_in[23],
        (const float*)d_in[25], (const float*)d_in[26], (const float*)d_in[27],
        (const float*)d_in[29], (const float*)d_in[30], (const float*)d_in[31],
        (float*)d_out);
}